// round 8
// baseline (speedup 1.0000x reference)
#include <cuda_runtime.h>

#define NLEV   12
#define HSIZE  524288
#define HMASK  (HSIZE - 1)

// duplicated {w,w} layout, float offsets (all even -> 8B aligned pairs)
#define OFF_W1  0       // 32*24*2 = 1536
#define OFF_B1  1536    // 32*2   = 64
#define OFF_W2  1600    // 16*32*2= 1024
#define OFF_B2  2624    // 16*2   = 32
#define OFF_W3  2656    // 8*16*2 = 256
#define OFF_B3  2912    // 8*2    = 16
#define OFF_W4  2928    // 8*2    = 16
#define OFF_B4  2944    // 1*2    = 2
#define NW_FLOATS 2948

__constant__ float cW[NW_FLOATS];
__device__  float g_dup[NW_FLOATS];

union F2 { unsigned long long u; float2 f; float s[2]; };

__device__ __forceinline__ void fma2(F2& d, const F2 a, const F2 b, const F2 c) {
    asm("fma.rn.f32x2 %0, %1, %2, %3;" : "=l"(d.u) : "l"(a.u), "l"(b.u), "l"(c.u));
}

// one 64-bit constant load -> register pair, no pack MOVs
__device__ __forceinline__ F2 cpair(int floatOff) {
    F2 r;
    r.u = *reinterpret_cast<const unsigned long long*>(cW + floatOff);
    return r;
}

__device__ __forceinline__ F2 lrelu2(F2 v, const F2 slope) {
    F2 m, r;
    asm("mul.rn.f32x2 %0, %1, %2;" : "=l"(m.u) : "l"(v.u), "l"(slope.u));
    r.s[0] = fmaxf(v.s[0], m.s[0]);
    r.s[1] = fmaxf(v.s[1], m.s[1]);
    return r;
}

// duplicate raw weights into {w,w} pairs in g_dup
__global__ void prep_kernel(const float* __restrict__ W1, const float* __restrict__ b1,
                            const float* __restrict__ W2, const float* __restrict__ b2,
                            const float* __restrict__ W3, const float* __restrict__ b3,
                            const float* __restrict__ W4, const float* __restrict__ b4)
{
    int k = blockIdx.x * blockDim.x + threadIdx.x;
    float w; int off;
    if      (k < 768)  { w = W1[k];        off = OFF_W1 + 2 * k; }
    else if (k < 800)  { w = b1[k - 768];  off = OFF_B1 + 2 * (k - 768); }
    else if (k < 1312) { w = W2[k - 800];  off = OFF_W2 + 2 * (k - 800); }
    else if (k < 1328) { w = b2[k - 1312]; off = OFF_B2 + 2 * (k - 1312); }
    else if (k < 1456) { w = W3[k - 1328]; off = OFF_W3 + 2 * (k - 1328); }
    else if (k < 1464) { w = b3[k - 1456]; off = OFF_B3 + 2 * (k - 1456); }
    else if (k < 1472) { w = W4[k - 1464]; off = OFF_W4 + 2 * (k - 1464); }
    else if (k < 1473) { w = b4[0];        off = OFF_B4; }
    else return;
    g_dup[off]     = w;
    g_dup[off + 1] = w;
}

__global__ __launch_bounds__(128, 6)
void nhgrid_kernel(const float* __restrict__ x,
                   const float* __restrict__ tables,
                   float* __restrict__ out, int n_points)
{
    int pair = blockIdx.x * blockDim.x + threadIdx.x;
    int n0 = 2 * pair;
    if (n0 >= n_points) return;
    bool full = (n0 + 1 < n_points);

    float ax, ay, bx, by;
    if (full) {
        float4 pp = *reinterpret_cast<const float4*>(x + 2 * n0);
        ax = pp.x; ay = pp.y; bx = pp.z; by = pp.w;
    } else {
        ax = x[2 * n0]; ay = x[2 * n0 + 1]; bx = ax; by = ay;
    }
    float a0 = ax * 0.5f + 0.5f, a1 = ay * 0.5f + 0.5f;
    float c0 = bx * 0.5f + 0.5f, c1 = by * 0.5f + 0.5f;

    F2 slope; slope.s[0] = 0.01f; slope.s[1] = 0.01f;

    // spacings = 256.0 // 1.6**(11-i), Python-double floor-division semantics
    const float spacings[NLEV] = {1.f, 2.f, 3.f, 5.f, 9.f, 15.f, 24.f, 39.f,
                                  62.f, 99.f, 159.f, 256.f};

    F2 f[2 * NLEV];
    #pragma unroll
    for (int i = 0; i < NLEV; i++) {
        float s = spacings[i];
        int da0 = (int)floorf(a0 * s);
        int da1 = (int)floorf(a1 * s);
        int db0 = (int)floorf(c0 * s);
        int db1 = (int)floorf(c1 * s);
        unsigned ha = ((unsigned)da0 * 73856093u + (unsigned)da1 * 19349663u) & HMASK;
        unsigned hb = ((unsigned)db0 * 73856093u + (unsigned)db1 * 19349663u) & HMASK;
        const float2* base = reinterpret_cast<const float2*>(tables) + (size_t)i * HSIZE;
        float2 t0 = base[ha];
        float2 t1 = base[hb];
        f[2 * i].f     = make_float2(t0.x, t1.x);
        f[2 * i + 1].f = make_float2(t0.y, t1.y);
    }

    // layer 1: 24 -> 32, j-outer so feature pairs die progressively
    F2 h1[32];
    #pragma unroll
    for (int i = 0; i < 32; i++) h1[i] = cpair(OFF_B1 + 2 * i);
    #pragma unroll
    for (int j = 0; j < 24; j++) {
        F2 fj = f[j];
        #pragma unroll
        for (int i = 0; i < 32; i++) {
            fma2(h1[i], cpair(OFF_W1 + i * 48 + 2 * j), fj, h1[i]);
        }
    }
    #pragma unroll
    for (int i = 0; i < 32; i++) h1[i] = lrelu2(h1[i], slope);

    // layer 2: 32 -> 16, j-outer so h1 pairs die progressively
    F2 h2[16];
    #pragma unroll
    for (int i = 0; i < 16; i++) h2[i] = cpair(OFF_B2 + 2 * i);
    #pragma unroll
    for (int j = 0; j < 32; j++) {
        F2 hj = h1[j];
        #pragma unroll
        for (int i = 0; i < 16; i++) {
            fma2(h2[i], cpair(OFF_W2 + i * 64 + 2 * j), hj, h2[i]);
        }
    }
    #pragma unroll
    for (int i = 0; i < 16; i++) h2[i] = lrelu2(h2[i], slope);

    // layer 3: 16 -> 8
    F2 h3[8];
    #pragma unroll
    for (int i = 0; i < 8; i++) h3[i] = cpair(OFF_B3 + 2 * i);
    #pragma unroll
    for (int j = 0; j < 16; j++) {
        F2 hj = h2[j];
        #pragma unroll
        for (int i = 0; i < 8; i++) {
            fma2(h3[i], cpair(OFF_W3 + i * 32 + 2 * j), hj, h3[i]);
        }
    }
    #pragma unroll
    for (int i = 0; i < 8; i++) h3[i] = lrelu2(h3[i], slope);

    // layer 4: 8 -> 1, then double lrelu
    F2 z = cpair(OFF_B4);
    #pragma unroll
    for (int j = 0; j < 8; j++) {
        fma2(z, cpair(OFF_W4 + 2 * j), h3[j], z);
    }
    z = lrelu2(z, slope);
    z = lrelu2(z, slope);

    if (full) {
        *reinterpret_cast<float2*>(out + n0) = z.f;
    } else {
        out[n0] = z.s[0];
    }
}

extern "C" void kernel_launch(void* const* d_in, const int* in_sizes, int n_in,
                              void* d_out, int out_size)
{
    const float* x      = (const float*)d_in[0];
    const float* tables = (const float*)d_in[1];
    const float* W1     = (const float*)d_in[2];
    const float* b1     = (const float*)d_in[3];
    const float* W2     = (const float*)d_in[4];
    const float* b2     = (const float*)d_in[5];
    const float* W3     = (const float*)d_in[6];
    const float* b3     = (const float*)d_in[7];
    const float* W4     = (const float*)d_in[8];
    const float* b4     = (const float*)d_in[9];
    float* out = (float*)d_out;

    int n_points = in_sizes[0] / 2;

    // 1) build duplicated weight layout in device global
    prep_kernel<<<(1473 + 255) / 256, 256>>>(W1, b1, W2, b2, W3, b3, W4, b4);

    // 2) move it into constant memory (D2D async memcpy, graph-capturable)
    void* dup_ptr = nullptr;
    cudaGetSymbolAddress(&dup_ptr, g_dup);
    cudaMemcpyToSymbolAsync(cW, dup_ptr, NW_FLOATS * sizeof(float), 0,
                            cudaMemcpyDeviceToDevice, 0);

    // 3) main kernel
    int n_pairs = (n_points + 1) / 2;
    int threads = 128;
    int blocks = (n_pairs + threads - 1) / threads;
    nhgrid_kernel<<<blocks, threads>>>(x, tables, out, n_points);
}

// round 9
// speedup vs baseline: 9.2532x; 9.2532x over previous
#include <cuda_runtime.h>

#define NLEV   12
#define HSIZE  524288
#define HMASK  (HSIZE - 1)

// TRANSPOSED duplicated {w,w} layout, float offsets (all even -> 8B aligned)
// W1T[j][i]: j=0..23 feature, i=0..31 output  -> OFF_W1 + (j*32+i)*2
// W2T[j][i]: j=0..31, i=0..15                 -> OFF_W2 + (j*16+i)*2
// W3T[j][i]: j=0..15, i=0..7                  -> OFF_W3 + (j*8+i)*2
#define OFF_W1  0       // 24*32*2 = 1536
#define OFF_B1  1536    // 64
#define OFF_W2  1600    // 1024
#define OFF_B2  2624    // 32
#define OFF_W3  2656    // 256
#define OFF_B3  2912    // 16
#define OFF_W4  2928    // 16
#define OFF_B4  2944    // 2
#define NW_FLOATS 2948

__constant__ float cW[NW_FLOATS];
__device__  float g_dup[NW_FLOATS];

union F2 { unsigned long long u; float2 f; float s[2]; };

__device__ __forceinline__ void fma2(F2& d, const F2 a, const F2 b, const F2 c) {
    asm("fma.rn.f32x2 %0, %1, %2, %3;" : "=l"(d.u) : "l"(a.u), "l"(b.u), "l"(c.u));
}

// one 64-bit constant load -> register pair, no pack MOVs
__device__ __forceinline__ F2 cpair(int floatOff) {
    F2 r;
    r.u = *reinterpret_cast<const unsigned long long*>(cW + floatOff);
    return r;
}

__device__ __forceinline__ F2 lrelu2(F2 v, const F2 slope) {
    F2 m, r;
    asm("mul.rn.f32x2 %0, %1, %2;" : "=l"(m.u) : "l"(v.u), "l"(slope.u));
    r.s[0] = fmaxf(v.s[0], m.s[0]);
    r.s[1] = fmaxf(v.s[1], m.s[1]);
    return r;
}

// build transposed, duplicated weight layout in g_dup
__global__ void prep_kernel(const float* __restrict__ W1, const float* __restrict__ b1,
                            const float* __restrict__ W2, const float* __restrict__ b2,
                            const float* __restrict__ W3, const float* __restrict__ b3,
                            const float* __restrict__ W4, const float* __restrict__ b4)
{
    int k = blockIdx.x * blockDim.x + threadIdx.x;
    float w; int off;
    if (k < 768) {                       // W1 [32 x 24] -> W1T
        int i = k / 24, j = k % 24;
        w = W1[k]; off = OFF_W1 + (j * 32 + i) * 2;
    } else if (k < 800) {
        w = b1[k - 768]; off = OFF_B1 + 2 * (k - 768);
    } else if (k < 1312) {               // W2 [16 x 32] -> W2T
        int s = k - 800, i = s / 32, j = s % 32;
        w = W2[s]; off = OFF_W2 + (j * 16 + i) * 2;
    } else if (k < 1328) {
        w = b2[k - 1312]; off = OFF_B2 + 2 * (k - 1312);
    } else if (k < 1456) {               // W3 [8 x 16] -> W3T
        int s = k - 1328, i = s / 16, j = s % 16;
        w = W3[s]; off = OFF_W3 + (j * 8 + i) * 2;
    } else if (k < 1464) {
        w = b3[k - 1456]; off = OFF_B3 + 2 * (k - 1456);
    } else if (k < 1472) {
        w = W4[k - 1464]; off = OFF_W4 + 2 * (k - 1464);
    } else if (k < 1473) {
        w = b4[0]; off = OFF_B4;
    } else return;
    g_dup[off]     = w;
    g_dup[off + 1] = w;
}

__global__ __launch_bounds__(128, 5)
void nhgrid_kernel(const float* __restrict__ x,
                   const float* __restrict__ tables,
                   float* __restrict__ out, int n_points)
{
    int pair = blockIdx.x * blockDim.x + threadIdx.x;
    int n0 = 2 * pair;
    if (n0 >= n_points) return;
    bool full = (n0 + 1 < n_points);

    float ax, ay, bx, by;
    if (full) {
        float4 pp = *reinterpret_cast<const float4*>(x + 2 * n0);
        ax = pp.x; ay = pp.y; bx = pp.z; by = pp.w;
    } else {
        ax = x[2 * n0]; ay = x[2 * n0 + 1]; bx = ax; by = ay;
    }
    float a0 = ax * 0.5f + 0.5f, a1 = ay * 0.5f + 0.5f;
    float c0 = bx * 0.5f + 0.5f, c1 = by * 0.5f + 0.5f;

    F2 slope; slope.s[0] = 0.01f; slope.s[1] = 0.01f;

    // spacings = 256.0 // 1.6**(11-i), Python-double floor-division semantics
    const float spacings[NLEV] = {1.f, 2.f, 3.f, 5.f, 9.f, 15.f, 24.f, 39.f,
                                  62.f, 99.f, 159.f, 256.f};

    // layer-1 accumulators initialized with biases
    F2 h1[32];
    #pragma unroll
    for (int i = 0; i < 32; i++) h1[i] = cpair(OFF_B1 + 2 * i);

    // gather + accumulate in 2 chunks of 6 levels (12 feature pairs each):
    // keeps 12 gathers in flight for latency, features die right after use.
    #pragma unroll
    for (int c = 0; c < 2; c++) {
        F2 f[12];
        #pragma unroll
        for (int l = 0; l < 6; l++) {
            int lev = 6 * c + l;
            float s = spacings[lev];
            int da0 = (int)floorf(a0 * s);
            int da1 = (int)floorf(a1 * s);
            int db0 = (int)floorf(c0 * s);
            int db1 = (int)floorf(c1 * s);
            unsigned ha = ((unsigned)da0 * 73856093u + (unsigned)da1 * 19349663u) & HMASK;
            unsigned hb = ((unsigned)db0 * 73856093u + (unsigned)db1 * 19349663u) & HMASK;
            const float2* base = reinterpret_cast<const float2*>(tables) + (size_t)lev * HSIZE;
            float2 t0 = base[ha];
            float2 t1 = base[hb];
            f[2 * l].f     = make_float2(t0.x, t1.x);
            f[2 * l + 1].f = make_float2(t0.y, t1.y);
        }
        #pragma unroll
        for (int l = 0; l < 12; l++) {
            int j = 12 * c + l;            // global feature index
            F2 fj = f[l];
            #pragma unroll
            for (int i = 0; i < 32; i++) {
                fma2(h1[i], cpair(OFF_W1 + (j * 32 + i) * 2), fj, h1[i]);
            }
        }
    }
    #pragma unroll
    for (int i = 0; i < 32; i++) h1[i] = lrelu2(h1[i], slope);

    // layer 2: 32 -> 16, j-outer, transposed weights (contiguous per j), h1 dies progressively
    F2 h2[16];
    #pragma unroll
    for (int i = 0; i < 16; i++) h2[i] = cpair(OFF_B2 + 2 * i);
    #pragma unroll
    for (int j = 0; j < 32; j++) {
        F2 hj = h1[j];
        #pragma unroll
        for (int i = 0; i < 16; i++) {
            fma2(h2[i], cpair(OFF_W2 + (j * 16 + i) * 2), hj, h2[i]);
        }
    }
    #pragma unroll
    for (int i = 0; i < 16; i++) h2[i] = lrelu2(h2[i], slope);

    // layer 3: 16 -> 8
    F2 h3[8];
    #pragma unroll
    for (int i = 0; i < 8; i++) h3[i] = cpair(OFF_B3 + 2 * i);
    #pragma unroll
    for (int j = 0; j < 16; j++) {
        F2 hj = h2[j];
        #pragma unroll
        for (int i = 0; i < 8; i++) {
            fma2(h3[i], cpair(OFF_W3 + (j * 8 + i) * 2), hj, h3[i]);
        }
    }
    #pragma unroll
    for (int i = 0; i < 8; i++) h3[i] = lrelu2(h3[i], slope);

    // layer 4: 8 -> 1, then double lrelu
    F2 z = cpair(OFF_B4);
    #pragma unroll
    for (int j = 0; j < 8; j++) {
        fma2(z, cpair(OFF_W4 + 2 * j), h3[j], z);
    }
    z = lrelu2(z, slope);
    z = lrelu2(z, slope);

    if (full) {
        *reinterpret_cast<float2*>(out + n0) = z.f;
    } else {
        out[n0] = z.s[0];
    }
}

extern "C" void kernel_launch(void* const* d_in, const int* in_sizes, int n_in,
                              void* d_out, int out_size)
{
    const float* x      = (const float*)d_in[0];
    const float* tables = (const float*)d_in[1];
    const float* W1     = (const float*)d_in[2];
    const float* b1     = (const float*)d_in[3];
    const float* W2     = (const float*)d_in[4];
    const float* b2     = (const float*)d_in[5];
    const float* W3     = (const float*)d_in[6];
    const float* b3     = (const float*)d_in[7];
    const float* W4     = (const float*)d_in[8];
    const float* b4     = (const float*)d_in[9];
    float* out = (float*)d_out;

    int n_points = in_sizes[0] / 2;

    // 1) build transposed duplicated weight layout in device global
    prep_kernel<<<(1473 + 255) / 256, 256>>>(W1, b1, W2, b2, W3, b3, W4, b4);

    // 2) move it into constant memory (D2D async memcpy, graph-capturable)
    void* dup_ptr = nullptr;
    cudaGetSymbolAddress(&dup_ptr, g_dup);
    cudaMemcpyToSymbolAsync(cW, dup_ptr, NW_FLOATS * sizeof(float), 0,
                            cudaMemcpyDeviceToDevice, 0);

    // 3) main kernel
    int n_pairs = (n_points + 1) / 2;
    int threads = 128;
    int blocks = (n_pairs + threads - 1) / threads;
    nhgrid_kernel<<<blocks, threads>>>(x, tables, out, n_points);
}